// round 5
// baseline (speedup 1.0000x reference)
#include <cuda_runtime.h>
#include <math.h>

#define N_RAYS   262144
#define HIDDEN   256
#define MAX_ITERS 32
#define FAR_DIST 6.0f
#define HIT_T    1e-5f
#define PERT     1e-3f
#define THREADS  256

__global__ __launch_bounds__(THREADS)
void sphere_trace_render_kernel(const float* __restrict__ origins,
                                const float* __restrict__ directions,
                                const float* __restrict__ center,
                                const float* __restrict__ radius,
                                const float* __restrict__ W1,
                                const float* __restrict__ b1,
                                const float* __restrict__ W2,
                                const float* __restrict__ b2,
                                const float* __restrict__ Wc1,
                                const float* __restrict__ bc1,
                                const float* __restrict__ Wc2,
                                const float* __restrict__ bc2,
                                float* __restrict__ out)
{
    // Packed weights: one float4 per hidden unit -> broadcast LDS.128
    __shared__ float4 sW1[HIDDEN];   // (W1[0][i], W1[1][i], W1[2][i], b1[i])
    __shared__ float  sW2[HIDDEN];   // W2[i][0]
    __shared__ float4 sC1[HIDDEN];   // (Wc1[0][i], Wc1[1][i], Wc1[2][i], bc1[i])
    __shared__ float4 sC2[HIDDEN];   // (Wc2[i][0], Wc2[i][1], Wc2[i][2], 0)

    const int t = threadIdx.x;
    // THREADS == HIDDEN == 256: each thread stages exactly one unit's weights
    sW1[t] = make_float4(W1[t], W1[HIDDEN + t], W1[2 * HIDDEN + t], b1[t]);
    sW2[t] = W2[t];
    sC1[t] = make_float4(Wc1[t], Wc1[HIDDEN + t], Wc1[2 * HIDDEN + t], bc1[t]);
    sC2[t] = make_float4(Wc2[3 * t + 0], Wc2[3 * t + 1], Wc2[3 * t + 2], 0.0f);
    __syncthreads();

    const int ray = blockIdx.x * THREADS + t;  // grid sized exactly

    float px = origins[3 * ray + 0];
    float py = origins[3 * ray + 1];
    float pz = origins[3 * ray + 2];
    const float dx = directions[3 * ray + 0];
    const float dy = directions[3 * ray + 1];
    const float dz = directions[3 * ray + 2];

    const float cx  = center[0];
    const float cy  = center[1];
    const float cz  = center[2];
    const float rad = radius[0];
    const float bb2 = b2[0];
    const float bo0 = bc2[0];
    const float bo1 = bc2[1];
    const float bo2 = bc2[2];

    float dist = 0.0f;
    bool  unfinished = true;
    bool  hit = false;

    for (int it = 0; it < MAX_ITERS; ++it) {
        // Warp-level early exit: all lanes converged here every iteration.
        if (__all_sync(0xFFFFFFFFu, !unfinished)) break;

        // Analytic sphere SDF — single change vs R1: norm with y^2 INNERMOST,
        // matching fadd(mul(x,x),mul(y,y)) -> fma(rx,rx, ry*ry), then
        // fadd(.,mul(z,z)) -> fma(rz,rz, .)  (left-mul fused).
        const float rx = px - cx, ry = py - cy, rz = pz - cz;
        const float base = sqrtf(fmaf(rz, rz, fmaf(rx, rx, __fmul_rn(ry, ry)))) - rad;

        // Perturbation MLP: relu(p@W1 + b1) @ W2, 4 independent accumulators for ILP
        float a0 = 0.0f, a1 = 0.0f, a2 = 0.0f, a3 = 0.0f;
        #pragma unroll 8
        for (int i = 0; i < HIDDEN; i += 4) {
            float4 w; float h;
            w = sW1[i + 0];
            h = fmaxf(fmaf(w.x, px, fmaf(w.y, py, fmaf(w.z, pz, w.w))), 0.0f);
            a0 = fmaf(h, sW2[i + 0], a0);
            w = sW1[i + 1];
            h = fmaxf(fmaf(w.x, px, fmaf(w.y, py, fmaf(w.z, pz, w.w))), 0.0f);
            a1 = fmaf(h, sW2[i + 1], a1);
            w = sW1[i + 2];
            h = fmaxf(fmaf(w.x, px, fmaf(w.y, py, fmaf(w.z, pz, w.w))), 0.0f);
            a2 = fmaf(h, sW2[i + 2], a2);
            w = sW1[i + 3];
            h = fmaxf(fmaf(w.x, px, fmaf(w.y, py, fmaf(w.z, pz, w.w))), 0.0f);
            a3 = fmaf(h, sW2[i + 3], a3);
        }
        const float d = base + PERT * tanhf(((a0 + a1) + (a2 + a3)) + bb2);

        // Exact reference mask semantics:
        //   curr_hit from this iteration's d; missed from dist BEFORE accumulation;
        //   hit wins even if missed; updates applied only where `still`.
        const bool curr_hit = fabsf(d) < HIT_T;
        const bool missed   = dist > FAR_DIST;
        hit = hit || (unfinished && curr_hit);
        const bool still = unfinished && !curr_hit && !missed;
        if (still) {
            px = fmaf(d, dx, px);
            py = fmaf(d, dy, py);
            pz = fmaf(d, dz, pz);
            dist += d;
        }
        unfinished = still;
    }

    // Color MLP only for hit rays; zeros otherwise (d_out is poisoned 0xAA)
    float r = 0.0f, g = 0.0f, b = 0.0f;
    if (hit) {
        float c0 = 0.0f, c1 = 0.0f, c2 = 0.0f;
        #pragma unroll 8
        for (int i = 0; i < HIDDEN; ++i) {
            const float4 w = sC1[i];
            const float  h =
                fmaxf(fmaf(w.x, px, fmaf(w.y, py, fmaf(w.z, pz, w.w))), 0.0f);
            const float4 v = sC2[i];
            c0 = fmaf(h, v.x, c0);
            c1 = fmaf(h, v.y, c1);
            c2 = fmaf(h, v.z, c2);
        }
        r = 1.0f / (1.0f + expf(-(c0 + bo0)));
        g = 1.0f / (1.0f + expf(-(c1 + bo1)));
        b = 1.0f / (1.0f + expf(-(c2 + bo2)));
    }
    out[3 * ray + 0] = r;
    out[3 * ray + 1] = g;
    out[3 * ray + 2] = b;
}

extern "C" void kernel_launch(void* const* d_in, const int* in_sizes, int n_in,
                              void* d_out, int out_size)
{
    const float* origins    = (const float*)d_in[0];
    const float* directions = (const float*)d_in[1];
    const float* center     = (const float*)d_in[2];
    const float* radius     = (const float*)d_in[3];
    const float* W1         = (const float*)d_in[4];
    const float* b1         = (const float*)d_in[5];
    const float* W2         = (const float*)d_in[6];
    const float* b2         = (const float*)d_in[7];
    const float* Wc1        = (const float*)d_in[8];
    const float* bc1        = (const float*)d_in[9];
    const float* Wc2        = (const float*)d_in[10];
    const float* bc2        = (const float*)d_in[11];
    float* out = (float*)d_out;

    const int blocks = N_RAYS / THREADS;  // 1024
    sphere_trace_render_kernel<<<blocks, THREADS>>>(
        origins, directions, center, radius,
        W1, b1, W2, b2, Wc1, bc1, Wc2, bc2, out);
}

// round 6
// speedup vs baseline: 1.3628x; 1.3628x over previous
#include <cuda_runtime.h>
#include <math.h>

#define N_RAYS   262144
#define HIDDEN   256
#define MAX_ITERS 32
#define FAR_DIST 6.0f
#define HIT_T    1e-5f
#define PERT     1e-3f
#define THREADS  256
#define RPT      2                     // rays per thread

__global__ __launch_bounds__(THREADS)
void sphere_trace_render_kernel(const float* __restrict__ origins,
                                const float* __restrict__ directions,
                                const float* __restrict__ center,
                                const float* __restrict__ radius,
                                const float* __restrict__ W1,
                                const float* __restrict__ b1,
                                const float* __restrict__ W2,
                                const float* __restrict__ b2,
                                const float* __restrict__ Wc1,
                                const float* __restrict__ bc1,
                                const float* __restrict__ Wc2,
                                const float* __restrict__ bc2,
                                float* __restrict__ out)
{
    // Packed weights: broadcast LDS.128, amortized over RPT rays per thread.
    __shared__ float4 sW1[HIDDEN];       // (W1[0][i], W1[1][i], W1[2][i], b1[i])
    __shared__ float4 sW2q[HIDDEN / 4];  // 4 consecutive W2 values per slot
    __shared__ float4 sC1[HIDDEN];       // (Wc1[0][i], Wc1[1][i], Wc1[2][i], bc1[i])
    __shared__ float4 sC2[HIDDEN];       // (Wc2[i][0], Wc2[i][1], Wc2[i][2], 0)

    const int t = threadIdx.x;
    sW1[t] = make_float4(W1[t], W1[HIDDEN + t], W1[2 * HIDDEN + t], b1[t]);
    if (t < HIDDEN / 4)
        sW2q[t] = make_float4(W2[4 * t + 0], W2[4 * t + 1], W2[4 * t + 2], W2[4 * t + 3]);
    sC1[t] = make_float4(Wc1[t], Wc1[HIDDEN + t], Wc1[2 * HIDDEN + t], bc1[t]);
    sC2[t] = make_float4(Wc2[3 * t + 0], Wc2[3 * t + 1], Wc2[3 * t + 2], 0.0f);
    __syncthreads();

    const int ray0 = blockIdx.x * (THREADS * RPT) + t;           // coalesced
    const int ray1 = ray0 + THREADS;

    float pxA = origins[3 * ray0 + 0], pyA = origins[3 * ray0 + 1], pzA = origins[3 * ray0 + 2];
    float pxB = origins[3 * ray1 + 0], pyB = origins[3 * ray1 + 1], pzB = origins[3 * ray1 + 2];
    const float dxA = directions[3 * ray0 + 0], dyA = directions[3 * ray0 + 1], dzA = directions[3 * ray0 + 2];
    const float dxB = directions[3 * ray1 + 0], dyB = directions[3 * ray1 + 1], dzB = directions[3 * ray1 + 2];

    const float cx  = center[0];
    const float cy  = center[1];
    const float cz  = center[2];
    const float rad = radius[0];
    const float bb2 = b2[0];
    const float bo0 = bc2[0];
    const float bo1 = bc2[1];
    const float bo2 = bc2[2];

    float distA = 0.0f, distB = 0.0f;
    bool  unfA = true, unfB = true;
    bool  hitA = false, hitB = false;

    for (int it = 0; it < MAX_ITERS; ++it) {
        if (__all_sync(0xFFFFFFFFu, !unfA && !unfB)) break;

        // ---- Geometry (FROZEN form from R5): norm = fma(rz,rz, fma(rx,rx, ry*ry))
        const float rxA = pxA - cx, ryA = pyA - cy, rzA = pzA - cz;
        const float baseA = sqrtf(fmaf(rzA, rzA, fmaf(rxA, rxA, __fmul_rn(ryA, ryA)))) - rad;
        const float rxB = pxB - cx, ryB = pyB - cy, rzB = pzB - cz;
        const float baseB = sqrtf(fmaf(rzB, rzB, fmaf(rxB, rxB, __fmul_rn(ryB, ryB)))) - rad;

        // ---- Perturbation MLP for both rays, weights loaded once per unit.
        float a0A = 0.0f, a1A = 0.0f, a2A = 0.0f, a3A = 0.0f;
        float a0B = 0.0f, a1B = 0.0f, a2B = 0.0f, a3B = 0.0f;
        #pragma unroll 8
        for (int i = 0; i < HIDDEN; i += 4) {
            const float4 q = sW2q[i >> 2];
            float4 w; float hA, hB;
            w = sW1[i + 0];
            hA = fmaxf(fmaf(w.x, pxA, fmaf(w.y, pyA, fmaf(w.z, pzA, w.w))), 0.0f);
            hB = fmaxf(fmaf(w.x, pxB, fmaf(w.y, pyB, fmaf(w.z, pzB, w.w))), 0.0f);
            a0A = fmaf(hA, q.x, a0A);  a0B = fmaf(hB, q.x, a0B);
            w = sW1[i + 1];
            hA = fmaxf(fmaf(w.x, pxA, fmaf(w.y, pyA, fmaf(w.z, pzA, w.w))), 0.0f);
            hB = fmaxf(fmaf(w.x, pxB, fmaf(w.y, pyB, fmaf(w.z, pzB, w.w))), 0.0f);
            a1A = fmaf(hA, q.y, a1A);  a1B = fmaf(hB, q.y, a1B);
            w = sW1[i + 2];
            hA = fmaxf(fmaf(w.x, pxA, fmaf(w.y, pyA, fmaf(w.z, pzA, w.w))), 0.0f);
            hB = fmaxf(fmaf(w.x, pxB, fmaf(w.y, pyB, fmaf(w.z, pzB, w.w))), 0.0f);
            a2A = fmaf(hA, q.z, a2A);  a2B = fmaf(hB, q.z, a2B);
            w = sW1[i + 3];
            hA = fmaxf(fmaf(w.x, pxA, fmaf(w.y, pyA, fmaf(w.z, pzA, w.w))), 0.0f);
            hB = fmaxf(fmaf(w.x, pxB, fmaf(w.y, pyB, fmaf(w.z, pzB, w.w))), 0.0f);
            a3A = fmaf(hA, q.w, a3A);  a3B = fmaf(hB, q.w, a3B);
        }
        const float dA = baseA + PERT * tanhf(((a0A + a1A) + (a2A + a3A)) + bb2);
        const float dB = baseB + PERT * tanhf(((a0B + a1B) + (a2B + a3B)) + bb2);

        // ---- Exact reference mask semantics (per ray, FROZEN from R5).
        {
            const bool curr_hit = fabsf(dA) < HIT_T;
            const bool missed   = distA > FAR_DIST;
            hitA = hitA || (unfA && curr_hit);
            const bool still = unfA && !curr_hit && !missed;
            if (still) {
                pxA = fmaf(dA, dxA, pxA);
                pyA = fmaf(dA, dyA, pyA);
                pzA = fmaf(dA, dzA, pzA);
                distA += dA;
            }
            unfA = still;
        }
        {
            const bool curr_hit = fabsf(dB) < HIT_T;
            const bool missed   = distB > FAR_DIST;
            hitB = hitB || (unfB && curr_hit);
            const bool still = unfB && !curr_hit && !missed;
            if (still) {
                pxB = fmaf(dB, dxB, pxB);
                pyB = fmaf(dB, dyB, pyB);
                pzB = fmaf(dB, dzB, pzB);
                distB += dB;
            }
            unfB = still;
        }
    }

    // ---- Color MLP for both rays (weights loaded once per unit).
    float rA = 0.0f, gA = 0.0f, bA = 0.0f;
    float rB = 0.0f, gB = 0.0f, bB = 0.0f;
    if (hitA || hitB) {
        float c0A = 0.0f, c1A = 0.0f, c2A = 0.0f;
        float c0B = 0.0f, c1B = 0.0f, c2B = 0.0f;
        #pragma unroll 8
        for (int i = 0; i < HIDDEN; ++i) {
            const float4 w = sC1[i];
            const float4 v = sC2[i];
            const float hA = fmaxf(fmaf(w.x, pxA, fmaf(w.y, pyA, fmaf(w.z, pzA, w.w))), 0.0f);
            const float hB = fmaxf(fmaf(w.x, pxB, fmaf(w.y, pyB, fmaf(w.z, pzB, w.w))), 0.0f);
            c0A = fmaf(hA, v.x, c0A);  c0B = fmaf(hB, v.x, c0B);
            c1A = fmaf(hA, v.y, c1A);  c1B = fmaf(hB, v.y, c1B);
            c2A = fmaf(hA, v.z, c2A);  c2B = fmaf(hB, v.z, c2B);
        }
        if (hitA) {
            rA = 1.0f / (1.0f + expf(-(c0A + bo0)));
            gA = 1.0f / (1.0f + expf(-(c1A + bo1)));
            bA = 1.0f / (1.0f + expf(-(c2A + bo2)));
        }
        if (hitB) {
            rB = 1.0f / (1.0f + expf(-(c0B + bo0)));
            gB = 1.0f / (1.0f + expf(-(c1B + bo1)));
            bB = 1.0f / (1.0f + expf(-(c2B + bo2)));
        }
    }
    out[3 * ray0 + 0] = rA;
    out[3 * ray0 + 1] = gA;
    out[3 * ray0 + 2] = bA;
    out[3 * ray1 + 0] = rB;
    out[3 * ray1 + 1] = gB;
    out[3 * ray1 + 2] = bB;
}

extern "C" void kernel_launch(void* const* d_in, const int* in_sizes, int n_in,
                              void* d_out, int out_size)
{
    const float* origins    = (const float*)d_in[0];
    const float* directions = (const float*)d_in[1];
    const float* center     = (const float*)d_in[2];
    const float* radius     = (const float*)d_in[3];
    const float* W1         = (const float*)d_in[4];
    const float* b1         = (const float*)d_in[5];
    const float* W2         = (const float*)d_in[6];
    const float* b2         = (const float*)d_in[7];
    const float* Wc1        = (const float*)d_in[8];
    const float* bc1        = (const float*)d_in[9];
    const float* Wc2        = (const float*)d_in[10];
    const float* bc2        = (const float*)d_in[11];
    float* out = (float*)d_out;

    const int blocks = N_RAYS / (THREADS * RPT);  // 512
    sphere_trace_render_kernel<<<blocks, THREADS>>>(
        origins, directions, center, radius,
        W1, b1, W2, b2, Wc1, bc1, Wc2, bc2, out);
}

// round 7
// speedup vs baseline: 1.5482x; 1.1360x over previous
#include <cuda_runtime.h>
#include <math.h>

#define N_RAYS   262144
#define HIDDEN   256
#define MAX_ITERS 32
#define FAR_DIST 6.0f
#define HIT_T    1e-5f
#define PERT     1e-3f
#define THREADS  256
#define RPT      2
#define NBKT     256

// Sorting scratch (allocation-free: device globals)
__device__ int g_hist[NBKT];
__device__ int g_off[NBKT];
__device__ int g_bucket[N_RAYS];
__device__ int g_perm[N_RAYS];

__global__ void zero_hist_kernel() { g_hist[threadIdx.x] = 0; }

// Key: difficulty ~ |impact_parameter - radius|; hard rays (grazing) bucket low.
// Hit side (b<rad) in buckets [0,128), miss side in [128,256) so the color-MLP
// branch is also warp-coherent after sorting.
__global__ void key_kernel(const float* __restrict__ origins,
                           const float* __restrict__ directions,
                           const float* __restrict__ center,
                           const float* __restrict__ radius)
{
    const int r = blockIdx.x * 256 + threadIdx.x;
    const float ox = origins[3 * r + 0] - center[0];
    const float oy = origins[3 * r + 1] - center[1];
    const float oz = origins[3 * r + 2] - center[2];
    const float dx = directions[3 * r + 0];
    const float dy = directions[3 * r + 1];
    const float dz = directions[3 * r + 2];
    const float tca = ox * dx + oy * dy + oz * dz;     // (signed) closest approach
    const float oc2 = ox * ox + oy * oy + oz * oz;
    const float b   = sqrtf(fmaxf(oc2 - tca * tca, 0.0f));
    const float rad = radius[0];
    const float key = fabsf(b - rad);
    const float u   = key / (key + 0.05f);             // compress: fine near 0
    int bkt = min(127, (int)(u * 128.0f));
    if (b >= rad) bkt += 128;
    g_bucket[r] = bkt;
    atomicAdd(&g_hist[bkt], 1);
}

__global__ void scan_kernel()
{
    __shared__ int s[NBKT];
    const int t = threadIdx.x;
    const int h = g_hist[t];
    s[t] = h;
    __syncthreads();
    for (int off = 1; off < NBKT; off <<= 1) {
        const int v = (t >= off) ? s[t - off] : 0;
        __syncthreads();
        s[t] += v;
        __syncthreads();
    }
    g_off[t] = s[t] - h;   // exclusive prefix
}

__global__ void scatter_kernel()
{
    const int r = blockIdx.x * 256 + threadIdx.x;
    const int pos = atomicAdd(&g_off[g_bucket[r]], 1);
    g_perm[pos] = r;
}

__global__ __launch_bounds__(THREADS)
void sphere_trace_render_kernel(const float* __restrict__ origins,
                                const float* __restrict__ directions,
                                const float* __restrict__ center,
                                const float* __restrict__ radius,
                                const float* __restrict__ W1,
                                const float* __restrict__ b1,
                                const float* __restrict__ W2,
                                const float* __restrict__ b2,
                                const float* __restrict__ Wc1,
                                const float* __restrict__ bc1,
                                const float* __restrict__ Wc2,
                                const float* __restrict__ bc2,
                                float* __restrict__ out)
{
    __shared__ float4 sW1[HIDDEN];       // (W1[0][i], W1[1][i], W1[2][i], b1[i])
    __shared__ float4 sW2q[HIDDEN / 4];  // 4 consecutive W2 values per slot
    __shared__ float4 sC1[HIDDEN];       // (Wc1[0][i], Wc1[1][i], Wc1[2][i], bc1[i])
    __shared__ float4 sC2[HIDDEN];       // (Wc2[i][0], Wc2[i][1], Wc2[i][2], 0)

    const int t = threadIdx.x;
    sW1[t] = make_float4(W1[t], W1[HIDDEN + t], W1[2 * HIDDEN + t], b1[t]);
    if (t < HIDDEN / 4)
        sW2q[t] = make_float4(W2[4 * t + 0], W2[4 * t + 1], W2[4 * t + 2], W2[4 * t + 3]);
    sC1[t] = make_float4(Wc1[t], Wc1[HIDDEN + t], Wc1[2 * HIDDEN + t], bc1[t]);
    sC2[t] = make_float4(Wc2[3 * t + 0], Wc2[3 * t + 1], Wc2[3 * t + 2], 0.0f);
    __syncthreads();

    // Difficulty-sorted ray ids: a warp's 64 rays have similar iteration counts.
    const int ray0 = g_perm[blockIdx.x * (THREADS * RPT) + t];
    const int ray1 = g_perm[blockIdx.x * (THREADS * RPT) + THREADS + t];

    float pxA = origins[3 * ray0 + 0], pyA = origins[3 * ray0 + 1], pzA = origins[3 * ray0 + 2];
    float pxB = origins[3 * ray1 + 0], pyB = origins[3 * ray1 + 1], pzB = origins[3 * ray1 + 2];
    const float dxA = directions[3 * ray0 + 0], dyA = directions[3 * ray0 + 1], dzA = directions[3 * ray0 + 2];
    const float dxB = directions[3 * ray1 + 0], dyB = directions[3 * ray1 + 1], dzB = directions[3 * ray1 + 2];

    const float cx  = center[0];
    const float cy  = center[1];
    const float cz  = center[2];
    const float rad = radius[0];
    const float bb2 = b2[0];
    const float bo0 = bc2[0];
    const float bo1 = bc2[1];
    const float bo2 = bc2[2];

    float distA = 0.0f, distB = 0.0f;
    bool  unfA = true, unfB = true;
    bool  hitA = false, hitB = false;

    for (int it = 0; it < MAX_ITERS; ++it) {
        if (__all_sync(0xFFFFFFFFu, !unfA && !unfB)) break;

        // ---- Geometry (FROZEN form): norm = fma(rz,rz, fma(rx,rx, ry*ry))
        const float rxA = pxA - cx, ryA = pyA - cy, rzA = pzA - cz;
        const float baseA = sqrtf(fmaf(rzA, rzA, fmaf(rxA, rxA, __fmul_rn(ryA, ryA)))) - rad;
        const float rxB = pxB - cx, ryB = pyB - cy, rzB = pzB - cz;
        const float baseB = sqrtf(fmaf(rzB, rzB, fmaf(rxB, rxB, __fmul_rn(ryB, ryB)))) - rad;

        // ---- Perturbation MLP for both rays, weights loaded once per unit.
        float a0A = 0.0f, a1A = 0.0f, a2A = 0.0f, a3A = 0.0f;
        float a0B = 0.0f, a1B = 0.0f, a2B = 0.0f, a3B = 0.0f;
        #pragma unroll 8
        for (int i = 0; i < HIDDEN; i += 4) {
            const float4 q = sW2q[i >> 2];
            float4 w; float hA, hB;
            w = sW1[i + 0];
            hA = fmaxf(fmaf(w.x, pxA, fmaf(w.y, pyA, fmaf(w.z, pzA, w.w))), 0.0f);
            hB = fmaxf(fmaf(w.x, pxB, fmaf(w.y, pyB, fmaf(w.z, pzB, w.w))), 0.0f);
            a0A = fmaf(hA, q.x, a0A);  a0B = fmaf(hB, q.x, a0B);
            w = sW1[i + 1];
            hA = fmaxf(fmaf(w.x, pxA, fmaf(w.y, pyA, fmaf(w.z, pzA, w.w))), 0.0f);
            hB = fmaxf(fmaf(w.x, pxB, fmaf(w.y, pyB, fmaf(w.z, pzB, w.w))), 0.0f);
            a1A = fmaf(hA, q.y, a1A);  a1B = fmaf(hB, q.y, a1B);
            w = sW1[i + 2];
            hA = fmaxf(fmaf(w.x, pxA, fmaf(w.y, pyA, fmaf(w.z, pzA, w.w))), 0.0f);
            hB = fmaxf(fmaf(w.x, pxB, fmaf(w.y, pyB, fmaf(w.z, pzB, w.w))), 0.0f);
            a2A = fmaf(hA, q.z, a2A);  a2B = fmaf(hB, q.z, a2B);
            w = sW1[i + 3];
            hA = fmaxf(fmaf(w.x, pxA, fmaf(w.y, pyA, fmaf(w.z, pzA, w.w))), 0.0f);
            hB = fmaxf(fmaf(w.x, pxB, fmaf(w.y, pyB, fmaf(w.z, pzB, w.w))), 0.0f);
            a3A = fmaf(hA, q.w, a3A);  a3B = fmaf(hB, q.w, a3B);
        }
        const float dA = baseA + PERT * tanhf(((a0A + a1A) + (a2A + a3A)) + bb2);
        const float dB = baseB + PERT * tanhf(((a0B + a1B) + (a2B + a3B)) + bb2);

        // ---- Exact reference mask semantics (FROZEN).
        {
            const bool curr_hit = fabsf(dA) < HIT_T;
            const bool missed   = distA > FAR_DIST;
            hitA = hitA || (unfA && curr_hit);
            const bool still = unfA && !curr_hit && !missed;
            if (still) {
                pxA = fmaf(dA, dxA, pxA);
                pyA = fmaf(dA, dyA, pyA);
                pzA = fmaf(dA, dzA, pzA);
                distA += dA;
            }
            unfA = still;
        }
        {
            const bool curr_hit = fabsf(dB) < HIT_T;
            const bool missed   = distB > FAR_DIST;
            hitB = hitB || (unfB && curr_hit);
            const bool still = unfB && !curr_hit && !missed;
            if (still) {
                pxB = fmaf(dB, dxB, pxB);
                pyB = fmaf(dB, dyB, pyB);
                pzB = fmaf(dB, dzB, pzB);
                distB += dB;
            }
            unfB = still;
        }
    }

    // ---- Color MLP (warp-coherent after sorting: miss-warps skip entirely).
    float rA = 0.0f, gA = 0.0f, bA = 0.0f;
    float rB = 0.0f, gB = 0.0f, bB = 0.0f;
    if (hitA || hitB) {
        float c0A = 0.0f, c1A = 0.0f, c2A = 0.0f;
        float c0B = 0.0f, c1B = 0.0f, c2B = 0.0f;
        #pragma unroll 8
        for (int i = 0; i < HIDDEN; ++i) {
            const float4 w = sC1[i];
            const float4 v = sC2[i];
            const float hA = fmaxf(fmaf(w.x, pxA, fmaf(w.y, pyA, fmaf(w.z, pzA, w.w))), 0.0f);
            const float hB = fmaxf(fmaf(w.x, pxB, fmaf(w.y, pyB, fmaf(w.z, pzB, w.w))), 0.0f);
            c0A = fmaf(hA, v.x, c0A);  c0B = fmaf(hB, v.x, c0B);
            c1A = fmaf(hA, v.y, c1A);  c1B = fmaf(hB, v.y, c1B);
            c2A = fmaf(hA, v.z, c2A);  c2B = fmaf(hB, v.z, c2B);
        }
        if (hitA) {
            rA = 1.0f / (1.0f + expf(-(c0A + bo0)));
            gA = 1.0f / (1.0f + expf(-(c1A + bo1)));
            bA = 1.0f / (1.0f + expf(-(c2A + bo2)));
        }
        if (hitB) {
            rB = 1.0f / (1.0f + expf(-(c0B + bo0)));
            gB = 1.0f / (1.0f + expf(-(c1B + bo1)));
            bB = 1.0f / (1.0f + expf(-(c2B + bo2)));
        }
    }
    out[3 * ray0 + 0] = rA;
    out[3 * ray0 + 1] = gA;
    out[3 * ray0 + 2] = bA;
    out[3 * ray1 + 0] = rB;
    out[3 * ray1 + 1] = gB;
    out[3 * ray1 + 2] = bB;
}

extern "C" void kernel_launch(void* const* d_in, const int* in_sizes, int n_in,
                              void* d_out, int out_size)
{
    const float* origins    = (const float*)d_in[0];
    const float* directions = (const float*)d_in[1];
    const float* center     = (const float*)d_in[2];
    const float* radius     = (const float*)d_in[3];
    const float* W1         = (const float*)d_in[4];
    const float* b1         = (const float*)d_in[5];
    const float* W2         = (const float*)d_in[6];
    const float* b2         = (const float*)d_in[7];
    const float* Wc1        = (const float*)d_in[8];
    const float* bc1        = (const float*)d_in[9];
    const float* Wc2        = (const float*)d_in[10];
    const float* bc2        = (const float*)d_in[11];
    float* out = (float*)d_out;

    // Difficulty sort (counting sort, allocation-free, graph-capturable)
    zero_hist_kernel<<<1, NBKT>>>();
    key_kernel<<<N_RAYS / 256, 256>>>(origins, directions, center, radius);
    scan_kernel<<<1, NBKT>>>();
    scatter_kernel<<<N_RAYS / 256, 256>>>();

    const int blocks = N_RAYS / (THREADS * RPT);  // 512
    sphere_trace_render_kernel<<<blocks, THREADS>>>(
        origins, directions, center, radius,
        W1, b1, W2, b2, Wc1, bc1, Wc2, bc2, out);
}

// round 8
// speedup vs baseline: 2.2501x; 1.4534x over previous
#include <cuda_runtime.h>
#include <math.h>

#define N_RAYS   262144
#define HIDDEN   256
#define MAX_ITERS 32
#define FAR_DIST 6.0f
#define HIT_T    1e-5f
#define PERT     1e-3f
#define THREADS  256
#define RPT      2
#define NBKT     256
#define NBLK     (N_RAYS / 256)   // 1024 key blocks

// Sorting scratch (allocation-free: device globals)
__device__ int g_bucket[N_RAYS];
__device__ int g_perm[N_RAYS];
__device__ int g_blockhist[NBLK * NBKT];   // [blk][bucket], coalesced writes
__device__ int g_blockbase[NBKT * NBLK];   // [bucket][blk], within-bucket excl prefix
__device__ int g_tot[NBKT];
__device__ int g_bucketbase[NBKT];

// ---- Phase 1: bucket keys + per-block histograms (no global atomics) ----
__global__ void key_blockhist_kernel(const float* __restrict__ origins,
                                     const float* __restrict__ directions,
                                     const float* __restrict__ center,
                                     const float* __restrict__ radius)
{
    __shared__ int s_hist[NBKT];
    const int t = threadIdx.x;
    s_hist[t] = 0;
    __syncthreads();

    const int r = blockIdx.x * 256 + t;
    const float ox = origins[3 * r + 0] - center[0];
    const float oy = origins[3 * r + 1] - center[1];
    const float oz = origins[3 * r + 2] - center[2];
    const float dx = directions[3 * r + 0];
    const float dy = directions[3 * r + 1];
    const float dz = directions[3 * r + 2];
    const float tca = ox * dx + oy * dy + oz * dz;
    const float oc2 = ox * ox + oy * oy + oz * oz;
    const float b   = sqrtf(fmaxf(oc2 - tca * tca, 0.0f));
    const float key = fabsf(b - radius[0]);
    const float u   = key / (key + 0.05f);            // compress: fine near 0
    int bkt = min(127, (int)(u * 128.0f));
    if (b >= radius[0]) bkt += 128;                   // hit side vs miss side
    g_bucket[r] = bkt;
    atomicAdd(&s_hist[bkt], 1);                       // shared atomics only
    __syncthreads();
    g_blockhist[blockIdx.x * NBKT + t] = s_hist[t];   // coalesced
}

// ---- Phase 2: per-bucket scan over 1024 block counts ----
__global__ void bucket_scan_kernel()
{
    __shared__ int s[NBLK];
    const int bucket = blockIdx.x;
    const int t = threadIdx.x;                        // 1024 threads
    const int c = g_blockhist[t * NBKT + bucket];
    s[t] = c;
    __syncthreads();
    #pragma unroll
    for (int off = 1; off < NBLK; off <<= 1) {
        const int v = (t >= off) ? s[t - off] : 0;
        __syncthreads();
        s[t] += v;
        __syncthreads();
    }
    g_blockbase[bucket * NBLK + t] = s[t] - c;        // exclusive within bucket
    if (t == NBLK - 1) g_tot[bucket] = s[t];
}

// ---- Phase 3: scan of bucket totals ----
__global__ void total_scan_kernel()
{
    __shared__ int s[NBKT];
    const int t = threadIdx.x;
    const int h = g_tot[t];
    s[t] = h;
    __syncthreads();
    #pragma unroll
    for (int off = 1; off < NBKT; off <<= 1) {
        const int v = (t >= off) ? s[t - off] : 0;
        __syncthreads();
        s[t] += v;
        __syncthreads();
    }
    g_bucketbase[t] = s[t] - h;
}

// ---- Phase 4: scatter via shared-atomic local ranks (no global atomics) ----
__global__ void scatter_kernel()
{
    __shared__ int s_base[NBKT];
    __shared__ int s_cnt[NBKT];
    const int t = threadIdx.x;
    s_base[t] = g_bucketbase[t] + g_blockbase[t * NBLK + blockIdx.x];
    s_cnt[t] = 0;
    __syncthreads();
    const int r = blockIdx.x * 256 + t;
    const int bkt = g_bucket[r];
    const int lr = atomicAdd(&s_cnt[bkt], 1);
    g_perm[s_base[bkt] + lr] = r;
}

__global__ __launch_bounds__(THREADS)
void sphere_trace_render_kernel(const float* __restrict__ origins,
                                const float* __restrict__ directions,
                                const float* __restrict__ center,
                                const float* __restrict__ radius,
                                const float* __restrict__ W1,
                                const float* __restrict__ b1,
                                const float* __restrict__ W2,
                                const float* __restrict__ b2,
                                const float* __restrict__ Wc1,
                                const float* __restrict__ bc1,
                                const float* __restrict__ Wc2,
                                const float* __restrict__ bc2,
                                float* __restrict__ out)
{
    __shared__ float4 sW1[HIDDEN];       // (W1[0][i], W1[1][i], W1[2][i], b1[i])
    __shared__ float4 sW2q[HIDDEN / 4];  // 4 consecutive W2 values per slot
    __shared__ float4 sC1[HIDDEN];       // (Wc1[0][i], Wc1[1][i], Wc1[2][i], bc1[i])
    __shared__ float4 sC2[HIDDEN];       // (Wc2[i][0], Wc2[i][1], Wc2[i][2], 0)

    const int t = threadIdx.x;
    sW1[t] = make_float4(W1[t], W1[HIDDEN + t], W1[2 * HIDDEN + t], b1[t]);
    if (t < HIDDEN / 4)
        sW2q[t] = make_float4(W2[4 * t + 0], W2[4 * t + 1], W2[4 * t + 2], W2[4 * t + 3]);
    sC1[t] = make_float4(Wc1[t], Wc1[HIDDEN + t], Wc1[2 * HIDDEN + t], bc1[t]);
    sC2[t] = make_float4(Wc2[3 * t + 0], Wc2[3 * t + 1], Wc2[3 * t + 2], 0.0f);
    __syncthreads();

    // Difficulty-sorted ray ids: a warp's 64 rays have similar iteration counts.
    const int ray0 = g_perm[blockIdx.x * (THREADS * RPT) + t];
    const int ray1 = g_perm[blockIdx.x * (THREADS * RPT) + THREADS + t];

    float pxA = origins[3 * ray0 + 0], pyA = origins[3 * ray0 + 1], pzA = origins[3 * ray0 + 2];
    float pxB = origins[3 * ray1 + 0], pyB = origins[3 * ray1 + 1], pzB = origins[3 * ray1 + 2];
    const float dxA = directions[3 * ray0 + 0], dyA = directions[3 * ray0 + 1], dzA = directions[3 * ray0 + 2];
    const float dxB = directions[3 * ray1 + 0], dyB = directions[3 * ray1 + 1], dzB = directions[3 * ray1 + 2];

    const float cx  = center[0];
    const float cy  = center[1];
    const float cz  = center[2];
    const float rad = radius[0];
    const float bb2 = b2[0];
    const float bo0 = bc2[0];
    const float bo1 = bc2[1];
    const float bo2 = bc2[2];

    float distA = 0.0f, distB = 0.0f;
    bool  unfA = true, unfB = true;
    bool  hitA = false, hitB = false;

    for (int it = 0; it < MAX_ITERS; ++it) {
        if (__all_sync(0xFFFFFFFFu, !unfA && !unfB)) break;

        // ---- Geometry (FROZEN form): norm = fma(rz,rz, fma(rx,rx, ry*ry))
        const float rxA = pxA - cx, ryA = pyA - cy, rzA = pzA - cz;
        const float baseA = sqrtf(fmaf(rzA, rzA, fmaf(rxA, rxA, __fmul_rn(ryA, ryA)))) - rad;
        const float rxB = pxB - cx, ryB = pyB - cy, rzB = pzB - cz;
        const float baseB = sqrtf(fmaf(rzB, rzB, fmaf(rxB, rxB, __fmul_rn(ryB, ryB)))) - rad;

        // ---- Perturbation MLP for both rays, weights loaded once per unit.
        float a0A = 0.0f, a1A = 0.0f, a2A = 0.0f, a3A = 0.0f;
        float a0B = 0.0f, a1B = 0.0f, a2B = 0.0f, a3B = 0.0f;
        #pragma unroll 8
        for (int i = 0; i < HIDDEN; i += 4) {
            const float4 q = sW2q[i >> 2];
            float4 w; float hA, hB;
            w = sW1[i + 0];
            hA = fmaxf(fmaf(w.x, pxA, fmaf(w.y, pyA, fmaf(w.z, pzA, w.w))), 0.0f);
            hB = fmaxf(fmaf(w.x, pxB, fmaf(w.y, pyB, fmaf(w.z, pzB, w.w))), 0.0f);
            a0A = fmaf(hA, q.x, a0A);  a0B = fmaf(hB, q.x, a0B);
            w = sW1[i + 1];
            hA = fmaxf(fmaf(w.x, pxA, fmaf(w.y, pyA, fmaf(w.z, pzA, w.w))), 0.0f);
            hB = fmaxf(fmaf(w.x, pxB, fmaf(w.y, pyB, fmaf(w.z, pzB, w.w))), 0.0f);
            a1A = fmaf(hA, q.y, a1A);  a1B = fmaf(hB, q.y, a1B);
            w = sW1[i + 2];
            hA = fmaxf(fmaf(w.x, pxA, fmaf(w.y, pyA, fmaf(w.z, pzA, w.w))), 0.0f);
            hB = fmaxf(fmaf(w.x, pxB, fmaf(w.y, pyB, fmaf(w.z, pzB, w.w))), 0.0f);
            a2A = fmaf(hA, q.z, a2A);  a2B = fmaf(hB, q.z, a2B);
            w = sW1[i + 3];
            hA = fmaxf(fmaf(w.x, pxA, fmaf(w.y, pyA, fmaf(w.z, pzA, w.w))), 0.0f);
            hB = fmaxf(fmaf(w.x, pxB, fmaf(w.y, pyB, fmaf(w.z, pzB, w.w))), 0.0f);
            a3A = fmaf(hA, q.w, a3A);  a3B = fmaf(hB, q.w, a3B);
        }
        const float dA = baseA + PERT * tanhf(((a0A + a1A) + (a2A + a3A)) + bb2);
        const float dB = baseB + PERT * tanhf(((a0B + a1B) + (a2B + a3B)) + bb2);

        // ---- Exact reference mask semantics (FROZEN).
        {
            const bool curr_hit = fabsf(dA) < HIT_T;
            const bool missed   = distA > FAR_DIST;
            hitA = hitA || (unfA && curr_hit);
            const bool still = unfA && !curr_hit && !missed;
            if (still) {
                pxA = fmaf(dA, dxA, pxA);
                pyA = fmaf(dA, dyA, pyA);
                pzA = fmaf(dA, dzA, pzA);
                distA += dA;
            }
            unfA = still;
        }
        {
            const bool curr_hit = fabsf(dB) < HIT_T;
            const bool missed   = distB > FAR_DIST;
            hitB = hitB || (unfB && curr_hit);
            const bool still = unfB && !curr_hit && !missed;
            if (still) {
                pxB = fmaf(dB, dxB, pxB);
                pyB = fmaf(dB, dyB, pyB);
                pzB = fmaf(dB, dzB, pzB);
                distB += dB;
            }
            unfB = still;
        }
    }

    // ---- Color MLP (warp-coherent after sorting: miss-warps skip entirely).
    float rA = 0.0f, gA = 0.0f, bA = 0.0f;
    float rB = 0.0f, gB = 0.0f, bB = 0.0f;
    if (hitA || hitB) {
        float c0A = 0.0f, c1A = 0.0f, c2A = 0.0f;
        float c0B = 0.0f, c1B = 0.0f, c2B = 0.0f;
        #pragma unroll 8
        for (int i = 0; i < HIDDEN; ++i) {
            const float4 w = sC1[i];
            const float4 v = sC2[i];
            const float hA = fmaxf(fmaf(w.x, pxA, fmaf(w.y, pyA, fmaf(w.z, pzA, w.w))), 0.0f);
            const float hB = fmaxf(fmaf(w.x, pxB, fmaf(w.y, pyB, fmaf(w.z, pzB, w.w))), 0.0f);
            c0A = fmaf(hA, v.x, c0A);  c0B = fmaf(hB, v.x, c0B);
            c1A = fmaf(hA, v.y, c1A);  c1B = fmaf(hB, v.y, c1B);
            c2A = fmaf(hA, v.z, c2A);  c2B = fmaf(hB, v.z, c2B);
        }
        if (hitA) {
            rA = 1.0f / (1.0f + __expf(-(c0A + bo0)));
            gA = 1.0f / (1.0f + __expf(-(c1A + bo1)));
            bA = 1.0f / (1.0f + __expf(-(c2A + bo2)));
        }
        if (hitB) {
            rB = 1.0f / (1.0f + __expf(-(c0B + bo0)));
            gB = 1.0f / (1.0f + __expf(-(c1B + bo1)));
            bB = 1.0f / (1.0f + __expf(-(c2B + bo2)));
        }
    }
    out[3 * ray0 + 0] = rA;
    out[3 * ray0 + 1] = gA;
    out[3 * ray0 + 2] = bA;
    out[3 * ray1 + 0] = rB;
    out[3 * ray1 + 1] = gB;
    out[3 * ray1 + 2] = bB;
}

extern "C" void kernel_launch(void* const* d_in, const int* in_sizes, int n_in,
                              void* d_out, int out_size)
{
    const float* origins    = (const float*)d_in[0];
    const float* directions = (const float*)d_in[1];
    const float* center     = (const float*)d_in[2];
    const float* radius     = (const float*)d_in[3];
    const float* W1         = (const float*)d_in[4];
    const float* b1         = (const float*)d_in[5];
    const float* W2         = (const float*)d_in[6];
    const float* b2         = (const float*)d_in[7];
    const float* Wc1        = (const float*)d_in[8];
    const float* bc1        = (const float*)d_in[9];
    const float* Wc2        = (const float*)d_in[10];
    const float* bc2        = (const float*)d_in[11];
    float* out = (float*)d_out;

    // Counting sort by difficulty — zero global atomics, graph-capturable.
    key_blockhist_kernel<<<NBLK, 256>>>(origins, directions, center, radius);
    bucket_scan_kernel<<<NBKT, NBLK>>>();
    total_scan_kernel<<<1, NBKT>>>();
    scatter_kernel<<<NBLK, 256>>>();

    const int blocks = N_RAYS / (THREADS * RPT);  // 512
    sphere_trace_render_kernel<<<blocks, THREADS>>>(
        origins, directions, center, radius,
        W1, b1, W2, b2, Wc1, bc1, Wc2, bc2, out);
}